// round 15
// baseline (speedup 1.0000x reference)
#include <cuda_runtime.h>
#include <cuda_bf16.h>
#include <cuda_fp16.h>
#include <math.h>
#include <stdint.h>

// GAT forward, B=4 N=2048 F=128 H=8 D=64 C=32.
// Softmax trick: exp(lrelu(f1_i+f2_j))/exp(f1_i) = (f1_i+f2_j>0) ? exp(f2_j)
//   : exp(-0.8 f1_i)*exp(0.2 f2_j); exp(f1_i) cancels in softmax.
// R15: k3/k5 single-barrier pipelined tiles — A double-buffered; per tile:
// sync -> issue MMA(jt) -> compute weights(jt+1); weight ALU overlaps tensor.

#define BB 4
#define NN 2048
#define FF 128
#define DD 64
#define HH 8
#define CC 32
#define HD (HH*DD)

__device__ __align__(16) float2 g_F1R[BB*HH*NN];     // (f1, exp(-0.8 f1))
__device__ __align__(16) uint4  g_F2H[BB*HH*NN/2];   // per j-pair {f2,e,e02} fp16x2
__device__ __align__(16) float2 g_G1R[BB*NN];
__device__ __align__(16) uint4  g_G2H[BB*NN/2];
__device__ unsigned g_adjbT[BB*64*NN];               // bitmask, TRANSPOSED [b][word][row]
__device__ __align__(16) __half g_WhT[BB*HH*DD*NN];      // WhT fp16 [bh][d][j]
__device__ __align__(16) __half g_Wh2T[BB*CC*NN];        // Wh2T fp16 [b][c][j]
__device__ __align__(16) __nv_bfloat16 g_WT_hi[HH*DD*FF];  // WcatT [c][f] bf16 hi
__device__ __align__(16) __nv_bfloat16 g_WT_lo[HH*DD*FF];
__device__ __align__(16) __nv_bfloat16 g_h_hi[BB*NN*HD];   // h bf16 hi [bn][hd]
__device__ __align__(16) __nv_bfloat16 g_h_lo[BB*NN*HD];
__device__ __align__(16) __nv_bfloat16 g_WoT_hi[CC*HD];    // WoT [c][k] bf16 hi
__device__ __align__(16) __nv_bfloat16 g_WoT_lo[CC*HD];

__device__ __forceinline__ uint32_t smem_u32(const void* p) {
    uint32_t a;
    asm("{ .reg .u64 tmp; cvta.to.shared.u64 tmp, %1; cvt.u32.u64 %0, tmp; }"
        : "=r"(a) : "l"(p));
    return a;
}
__device__ __forceinline__ void ldsm_x4(uint32_t* r, uint32_t addr) {
    asm volatile("ldmatrix.sync.aligned.m8n8.x4.shared.b16 {%0,%1,%2,%3}, [%4];"
        : "=r"(r[0]), "=r"(r[1]), "=r"(r[2]), "=r"(r[3]) : "r"(addr));
}
// bf16 mma (k1/k4)
__device__ __forceinline__ void mma16816(float* c, const uint32_t* a, const uint32_t* b) {
    asm volatile(
        "mma.sync.aligned.m16n8k16.row.col.f32.bf16.bf16.f32 "
        "{%0,%1,%2,%3}, {%4,%5,%6,%7}, {%8,%9}, {%0,%1,%2,%3};"
        : "+f"(c[0]), "+f"(c[1]), "+f"(c[2]), "+f"(c[3])
        : "r"(a[0]), "r"(a[1]), "r"(a[2]), "r"(a[3]), "r"(b[0]), "r"(b[1]));
}
// fp16 mma (k3/k5)
__device__ __forceinline__ void mma16816h(float* c, const uint32_t* a, const uint32_t* b) {
    asm volatile(
        "mma.sync.aligned.m16n8k16.row.col.f32.f16.f16.f32 "
        "{%0,%1,%2,%3}, {%4,%5,%6,%7}, {%8,%9}, {%0,%1,%2,%3};"
        : "+f"(c[0]), "+f"(c[1]), "+f"(c[2]), "+f"(c[3])
        : "r"(a[0]), "r"(a[1]), "r"(a[2]), "r"(a[3]), "r"(b[0]), "r"(b[1]));
}
#define CP_ASYNC16(dst, src) \
    asm volatile("cp.async.cg.shared.global [%0], [%1], 16;" :: "r"(dst), "l"(src))
#define CP_COMMIT() asm volatile("cp.async.commit_group;" ::: "memory")
#define CP_WAIT(n)  asm volatile("cp.async.wait_group %0;" :: "n"(n) : "memory")

// split float pair -> bf16 hi/lo packed words
__device__ __forceinline__ void split2(float a, float b, uint32_t& hi, uint32_t& lo) {
    __nv_bfloat162 hp = __floats2bfloat162_rn(a, b);
    float2 hf = __bfloat1622float2(hp);
    __nv_bfloat162 lp = __floats2bfloat162_rn(a - hf.x, b - hf.y);
    hi = *reinterpret_cast<uint32_t*>(&hp);
    lo = *reinterpret_cast<uint32_t*>(&lp);
}
__device__ __forceinline__ uint32_t pk_h2(float a, float b) {
    __half2 hp = __floats2half2_rn(a, b);
    return *reinterpret_cast<uint32_t*>(&hp);
}
__device__ __forceinline__ uint32_t hgt2m(uint32_t a, uint32_t b) {
    return __hgt2_mask(*reinterpret_cast<__half2*>(&a),
                       *reinterpret_cast<__half2*>(&b));
}
__device__ __forceinline__ uint32_t hmul2u(uint32_t a, uint32_t b) {
    __half2 r = __hmul2(*reinterpret_cast<__half2*>(&a),
                        *reinterpret_cast<__half2*>(&b));
    return *reinterpret_cast<uint32_t*>(&r);
}
__device__ __forceinline__ uint32_t f2h2(float v) {
    __half2 r = __float2half2_rn(v);
    return *reinterpret_cast<uint32_t*>(&r);
}

// ---------------- KWS: W[h][f][d] -> WcatT[c][f] bf16 hi/lo ----------------
__global__ __launch_bounds__(256) void kws_split(const float* __restrict__ W) {
    int idx = blockIdx.x*256 + threadIdx.x;      // 0..16383 = c*32 + kg
    int c = idx >> 5, kg = idx & 31;
    int h = c >> 6, d = c & 63;
    float v[4];
    #pragma unroll
    for (int q = 0; q < 4; q++)
        v[q] = W[h*(FF*DD) + (kg*4 + q)*DD + d];
    uint32_t h0, l0, h1, l1;
    split2(v[0], v[1], h0, l0);
    split2(v[2], v[3], h1, l1);
    *reinterpret_cast<uint2*>(g_WT_hi + (size_t)c*FF + kg*4) = make_uint2(h0, h1);
    *reinterpret_cast<uint2*>(g_WT_lo + (size_t)c*FF + kg*4) = make_uint2(l0, l1);
}

// ---------------- K4W: Wo[k][c] -> WoT[c][k] bf16 hi/lo ----------------
__global__ __launch_bounds__(256) void k4w_split(const float* __restrict__ Wo) {
    int idx = blockIdx.x*256 + threadIdx.x;      // 0..4095 = c*128 + kg
    int c = idx >> 7, kg = idx & 127;
    float v[4];
    #pragma unroll
    for (int q = 0; q < 4; q++)
        v[q] = Wo[(kg*4 + q)*CC + c];
    uint32_t h0, l0, h1, l1;
    split2(v[0], v[1], h0, l0);
    split2(v[2], v[3], h1, l1);
    *reinterpret_cast<uint2*>(g_WoT_hi + (size_t)c*HD + kg*4) = make_uint2(h0, h1);
    *reinterpret_cast<uint2*>(g_WoT_lo + (size_t)c*HD + kg*4) = make_uint2(l0, l1);
}

// ---------------- K0: adjacency -> transposed bitmask (int4 + shfl-or) ----------------
__global__ __launch_bounds__(256) void k0_mask(const int* __restrict__ adj) {
    int gw = (blockIdx.x * 256 + threadIdx.x) >> 5;  // 0..8191 = b*2048+row
    int lane = threadIdx.x & 31;
    int b = gw >> 11, row = gw & 2047;
    const int4* ar4 = reinterpret_cast<const int4*>(adj + (size_t)gw * NN);
    int lg = lane & 7, wsel = lane >> 3;
    #pragma unroll 4
    for (int it = 0; it < 16; it++) {
        int4 v = ar4[it*32 + lane];
        unsigned nib = (v.x > 0 ? 1u : 0u) | (v.y > 0 ? 2u : 0u)
                     | (v.z > 0 ? 4u : 0u) | (v.w > 0 ? 8u : 0u);
        unsigned part = nib << (lg * 4);
        part |= __shfl_xor_sync(0xffffffffu, part, 1);
        part |= __shfl_xor_sync(0xffffffffu, part, 2);
        part |= __shfl_xor_sync(0xffffffffu, part, 4);
        if (lg == 0)
            g_adjbT[((b<<6) + it*4 + wsel)*NN + row] = part;
    }
}

// ---------------- K1: Wh = x @ Wcat (bf16 HMMA); fused WhT(fp16) + f1/f2 ----------------
#define K1_SMEM 55296
__global__ __launch_bounds__(256) void k1_hmma(const float* __restrict__ x,
                                               const float* __restrict__ a1,
                                               const float* __restrict__ a2) {
    extern __shared__ __align__(16) char smem[];
    uint32_t sb = smem_u32(smem);
    int t = threadIdx.x;
    int warp = t >> 5, lane = t & 31;
    int h = blockIdx.x;
    int m0 = blockIdx.y * 128;
    int b = m0 >> 11, nd0 = m0 & 2047;
    int bh = b*8 + h;

    float acc[8][4];
    #pragma unroll
    for (int n=0;n<8;n++){ acc[n][0]=0.f; acc[n][1]=0.f; acc[n][2]=0.f; acc[n][3]=0.f; }

    uint32_t aRow = (uint32_t)(warp*16 + (lane & 15)) * 144u + ((lane & 16) ? 16u : 0u);
    uint32_t bAddr = sb + 36864u + ((lane & 16) ? 9216u : 0u)
                   + (uint32_t)(lane & 7) * 144u + (uint32_t)(lane & 8) * 2u;

    int rA = t >> 1, hA = t & 1;
    int rB = t >> 2, cB = t & 3;

    #pragma unroll
    for (int kt = 0; kt < 2; kt++) {
        if (kt) __syncthreads();
        int k0 = kt * 64;
        {
            const float4* px = reinterpret_cast<const float4*>(
                x + (size_t)(m0 + rA)*FF + k0 + hA*32);
            uint32_t off = (uint32_t)rA*144u + (uint32_t)hA*64u;
            #pragma unroll
            for (int q = 0; q < 4; q++) {
                float4 v0 = px[q*2], v1 = px[q*2+1];
                uint32_t hw[4], lw[4];
                split2(v0.x, v0.y, hw[0], lw[0]);
                split2(v0.z, v0.w, hw[1], lw[1]);
                split2(v1.x, v1.y, hw[2], lw[2]);
                split2(v1.z, v1.w, hw[3], lw[3]);
                *reinterpret_cast<uint4*>(smem + off + q*16) =
                    *reinterpret_cast<uint4*>(hw);
                *reinterpret_cast<uint4*>(smem + 18432 + off + q*16) =
                    *reinterpret_cast<uint4*>(lw);
            }
        }
        {
            const __nv_bfloat16* ph = g_WT_hi + (size_t)(h*64 + rB)*FF + k0 + cB*16;
            const __nv_bfloat16* pl = g_WT_lo + (size_t)(h*64 + rB)*FF + k0 + cB*16;
            uint32_t off = (uint32_t)rB*144u + (uint32_t)cB*32u;
            #pragma unroll
            for (int q = 0; q < 2; q++) {
                *reinterpret_cast<uint4*>(smem + 36864 + off + q*16) =
                    *reinterpret_cast<const uint4*>(ph + q*8);
                *reinterpret_cast<uint4*>(smem + 46080 + off + q*16) =
                    *reinterpret_cast<const uint4*>(pl + q*8);
            }
        }
        __syncthreads();
        #pragma unroll
        for (int k = 0; k < 4; k++) {
            uint32_t kb = (uint32_t)k * 32u;
            uint32_t ah[4], al[4];
            ldsm_x4(ah, sb + 0     + aRow + kb);
            ldsm_x4(al, sb + 18432 + aRow + kb);
            #pragma unroll
            for (int n = 0; n < 8; n++) {
                uint32_t bf[4];
                ldsm_x4(bf, bAddr + (uint32_t)n*(8u*144u) + kb);
                mma16816(acc[n], ah, bf);
                mma16816(acc[n], ah, bf + 2);
                mma16816(acc[n], al, bf);
            }
        }
    }
    // ---- fused epilogue: transpose, f1/f2 (+fp16 triplets), WhT fp16 ----
    __syncthreads();
    float* ts = reinterpret_cast<float*>(smem);          // [64 d][132]
    float* a1s = reinterpret_cast<float*>(smem + 33792);
    float* a2s = reinterpret_cast<float*>(smem + 34048);
    float* fse = reinterpret_cast<float*>(smem + 34304); // 3 x 128
    if (t < 64) { a1s[t] = a1[h*DD + t]; a2s[t] = a2[h*DD + t]; }
    int r0 = warp*16 + (lane >> 2);
    int r1 = r0 + 8;
    #pragma unroll
    for (int n = 0; n < 8; n++) {
        int c = n*8 + (lane & 3)*2;
        ts[c*132 + r0]     = acc[n][0];
        ts[(c+1)*132 + r0] = acc[n][1];
        ts[c*132 + r1]     = acc[n][2];
        ts[(c+1)*132 + r1] = acc[n][3];
    }
    __syncthreads();
    if (t < 128) {
        float f1 = 0.f, f2 = 0.f;
        #pragma unroll
        for (int d = 0; d < 64; d++) {
            float wv = ts[d*132 + t];
            f1 += wv * a1s[d];
            f2 += wv * a2s[d];
        }
        int tid = bh*NN + nd0 + t;
        g_F1R[tid] = make_float2(f1, expf(-0.8f*f1));
        fse[t]       = f2;
        fse[128 + t] = expf(f2);
        fse[256 + t] = expf(0.2f*f2);
    }
    #pragma unroll
    for (int q = 0; q < 4; q++) {
        int task = t + q*256;
        int d = task >> 4, nc = task & 15;
        uint32_t hw[4];
        #pragma unroll
        for (int p = 0; p < 4; p++)
            hw[p] = pk_h2(ts[d*132 + nc*8 + 2*p], ts[d*132 + nc*8 + 2*p + 1]);
        size_t off = ((size_t)bh*DD + d)*NN + nd0 + nc*8;
        *reinterpret_cast<uint4*>(g_WhT + off) = *reinterpret_cast<uint4*>(hw);
    }
    __syncthreads();
    if (t < 64) {
        uint4 o;
        o.x = pk_h2(fse[2*t],       fse[2*t + 1]);
        o.y = pk_h2(fse[128 + 2*t], fse[128 + 2*t + 1]);
        o.z = pk_h2(fse[256 + 2*t], fse[256 + 2*t + 1]);
        o.w = 0;
        g_F2H[(size_t)bh*(NN/2) + nd0/2 + t] = o;
    }
}

// ---- k3/k5 weight phase: triplets -> masked fp16 weights into A[abuf] ----
__device__ __forceinline__ void wphase4(char* smem, uint32_t aoff,
        const uint4* fp, unsigned bw, uint32_t negh, uint32_t rmulh, int nq) {
    #pragma unroll
    for (int pq = 0; pq < 4; pq++) {
        if (pq >= nq) break;
        uint32_t wv[4];
        #pragma unroll
        for (int p = 0; p < 4; p++) {
            uint4 tr = fp[pq*4 + p];
            uint32_t mgt = hgt2m(tr.x, negh);
            uint32_t alt = hmul2u(rmulh, tr.z);
            uint32_t sel = (tr.y & mgt) | (alt & ~mgt);
            uint32_t bits = (bw >> ((pq*4 + p)*2)) & 3u;
            uint32_t am = ((bits & 1u) ? 0xFFFFu : 0u)
                        | ((bits & 2u) ? 0xFFFF0000u : 0u);
            wv[p] = sel & am;
        }
        *reinterpret_cast<uint4*>(smem + aoff + (uint32_t)pq*16u) =
            make_uint4(wv[0], wv[1], wv[2], wv[3]);
    }
}

// ---------------- K3: layer-1 attention, pipelined single-barrier tiles ----------------
// smem: A0 @0, A1 @18432 (128x72 fp16 each); B0 @36864, B1 @46080 (64x72);
// f2s @55296 (uint4[2][32]). Total 56320.
#define K3_SMEM 56320
__global__ __launch_bounds__(256) void k3_attn1_mma() {
    extern __shared__ __align__(16) char smem[];
    uint4* f2s = reinterpret_cast<uint4*>(smem + 55296);
    uint32_t sb = smem_u32(smem);

    int t = threadIdx.x;
    int warp = t >> 5, lane = t & 31;
    int i0 = blockIdx.x * 128;
    int h = blockIdx.y, b = blockIdx.z;
    int bh = (b<<3) + h;

    int i = t & 127, jh = t >> 7;
    float2 f1r = g_F1R[bh*NN + i0 + i];
    uint32_t negf1h = f2h2(-f1r.x);
    uint32_t rmulh  = f2h2(f1r.y);
    const __half* bsrc = g_WhT + (size_t)bh*DD*NN;
    const uint4* f2g = g_F2H + (size_t)bh*(NN/2);
    const unsigned* adjb = g_adjbT + ((size_t)(b<<6))*NN + i0 + i;

    float acc[8][4];
    #pragma unroll
    for (int n=0;n<8;n++){ acc[n][0]=0.f; acc[n][1]=0.f; acc[n][2]=0.f; acc[n][3]=0.f; }
    float accz[4] = {0.f, 0.f, 0.f, 0.f};
    uint32_t bzf[2];
    bzf[0] = (lane < 4) ? 0x3C003C00u : 0u;   // ones column
    bzf[1] = bzf[0];

    int m0 = warp * 16;
    uint32_t aRow = (uint32_t)(m0 + (lane & 15)) * 144u + ((lane & 16) ? 16u : 0u);
    uint32_t bFrag = (uint32_t)(lane & 7) * 144u + ((lane & 16) ? 1152u : 0u)
                   + (uint32_t)(lane & 8) * 2u;
    uint32_t aWr = (uint32_t)i*144u + (uint32_t)jh*64u;   // weight-store base

    int dB = t >> 2, cB = t & 3;
    const __half* pB = bsrc + (size_t)dB*NN + cB*16;
    uint32_t bStOff = (uint32_t)dB*144u + (uint32_t)cB*32u;

    // ---- prologue: cp.async B(0); stage f2s(0); weights(0)->A0; stage f2s(1) ----
    {
        uint32_t d0 = sb + 36864u + bStOff;
        CP_ASYNC16(d0,      pB);
        CP_ASYNC16(d0 + 16, pB + 8);
        CP_COMMIT();
    }
    if (t < 32) f2s[t] = __ldg(&f2g[t]);
    __syncthreads();
    wphase4(smem, aWr, &f2s[jh*16], adjb[jh*NN], negf1h, rmulh, 4);
    if (t < 32) f2s[32 + t] = __ldg(&f2g[32 + t]);

    for (int jt = 0; jt < 32; jt++) {
        int pb = jt & 1;
        CP_WAIT(0);                     // B(jt) arrived
        __syncthreads();                // A(jt), f2s(jt+1), B(jt) visible
        if (jt < 31) {                  // cp.async B(jt+1) -> other buf
            uint32_t dN = sb + 36864u + (uint32_t)(pb^1)*9216u + bStOff;
            const __half* s = pB + (jt+1)*64;
            CP_ASYNC16(dN,      s);
            CP_ASYNC16(dN + 16, s + 8);
            CP_COMMIT();
        }
        // ---- MMA(jt): issue first (tensor pipe busy while weights run) ----
        uint32_t aBase = sb + (uint32_t)pb*18432u + aRow;
        uint32_t bBase = sb + 36864u + (uint32_t)pb*9216u + bFrag;
        #pragma unroll
        for (int k = 0; k < 4; k++) {
            uint32_t kb = (uint32_t)k * 32u;
            uint32_t ah[4];
            ldsm_x4(ah, aBase + kb);
            mma16816h(accz, ah, bzf);
            #pragma unroll
            for (int q = 0; q < 4; q++) {
                uint32_t bf[4];
                ldsm_x4(bf, bBase + (uint32_t)q*2304u + kb);
                mma16816h(acc[2*q],   ah, bf);
                mma16816h(acc[2*q+1], ah, bf + 2);
            }
        }
        // ---- weights(jt+1) -> A[pb^1] (overlaps MMA(jt) on tensor pipe) ----
        if (jt < 31) {
            wphase4(smem, (uint32_t)(pb^1)*18432u + aWr,
                    &f2s[(uint32_t)(pb^1)*32 + jh*16],
                    adjb[((jt+1)*2 + jh)*NN], negf1h, rmulh, 4);
        }
        // stage f2s(jt+2) into slot pb
        if (jt < 30 && t < 32)
            f2s[pb*32 + t] = __ldg(&f2g[(jt+2)*32 + t]);
    }
    // ---- epilogue: z via shfl; normalize + ELU; h bf16 hi/lo ----
    float z0 = __shfl_sync(0xffffffffu, accz[0], lane & 28);
    float z1 = __shfl_sync(0xffffffffu, accz[2], lane & 28);
    if (z0 < 1e-30f) z0 = 1.f;
    if (z1 < 1e-30f) z1 = 1.f;
    float invz0 = 1.f / z0, invz1 = 1.f / z1;
    int r0 = m0 + (lane >> 2);
    int r1 = r0 + 8;
    size_t base0 = (size_t)(b*NN + i0 + r0)*HD + h*DD + (lane & 3)*2;
    size_t base1 = (size_t)(b*NN + i0 + r1)*HD + h*DD + (lane & 3)*2;
    #pragma unroll
    for (int n = 0; n < 8; n++) {
        float v0 = acc[n][0] * invz0, v1 = acc[n][1] * invz0;
        float v2 = acc[n][2] * invz1, v3 = acc[n][3] * invz1;
        v0 = v0 > 0.f ? v0 : expm1f(v0);
        v1 = v1 > 0.f ? v1 : expm1f(v1);
        v2 = v2 > 0.f ? v2 : expm1f(v2);
        v3 = v3 > 0.f ? v3 : expm1f(v3);
        uint32_t h0, l0, h1, l1;
        split2(v0, v1, h0, l0);
        split2(v2, v3, h1, l1);
        *reinterpret_cast<uint32_t*>(g_h_hi + base0 + n*8) = h0;
        *reinterpret_cast<uint32_t*>(g_h_lo + base0 + n*8) = l0;
        *reinterpret_cast<uint32_t*>(g_h_hi + base1 + n*8) = h1;
        *reinterpret_cast<uint32_t*>(g_h_lo + base1 + n*8) = l1;
    }
}

// ---------------- K4: Wh2 = h @ Wo (bf16 HMMA); fused Wh2T(fp16) + g1/g2 ----------------
__global__ __launch_bounds__(256) void k4_hmma(const float* __restrict__ ao1,
                                               const float* __restrict__ ao2) {
    __shared__ __align__(16) char Ahp[64*144];
    __shared__ __align__(16) char Alp[64*144];
    __shared__ __align__(16) char Bs[2*32*144];   // hi @0, lo @4608
    uint32_t sbA_h = smem_u32(Ahp), sbA_l = smem_u32(Alp);
    uint32_t sbB = smem_u32(Bs);

    int t = threadIdx.x;
    int warp = t >> 5, lane = t & 31;
    int m0 = blockIdx.x * 64;
    int b = m0 >> 11, nd0 = m0 & 2047;
    int mt = warp >> 1, nh = warp & 1;

    float acc[2][4];
    acc[0][0]=0.f; acc[0][1]=0.f; acc[0][2]=0.f; acc[0][3]=0.f;
    acc[1][0]=0.f; acc[1][1]=0.f; acc[1][2]=0.f; acc[1][3]=0.f;

    uint32_t aRow = (uint32_t)(mt*16 + (lane & 15)) * 144u + ((lane & 16) ? 16u : 0u);
    uint32_t bAddr = sbB + ((lane & 16) ? 4608u : 0u)
                   + (uint32_t)(lane & 7) * 144u + (uint32_t)(lane & 8) * 2u;

    int rA = t >> 2, cA = t & 3;
    int rB = t >> 3, cB = t & 7;

    #pragma unroll
    for (int kt = 0; kt < 8; kt++) {
        if (kt) __syncthreads();
        int k0 = kt * 64;
        {
            const __nv_bfloat16* ph = g_h_hi + (size_t)(m0 + rA)*HD + k0 + cA*16;
            const __nv_bfloat16* pl = g_h_lo + (size_t)(m0 + rA)*HD + k0 + cA*16;
            uint32_t off = (uint32_t)rA*144u + (uint32_t)cA*32u;
            #pragma unroll
            for (int q = 0; q < 2; q++) {
                *reinterpret_cast<uint4*>(Ahp + off + q*16) =
                    *reinterpret_cast<const uint4*>(ph + q*8);
                *reinterpret_cast<uint4*>(Alp + off + q*16) =
                    *reinterpret_cast<const uint4*>(pl + q*8);
            }
        }
        {
            const __nv_bfloat16* ph = g_WoT_hi + (size_t)rB*HD + k0 + cB*8;
            const __nv_bfloat16* pl = g_WoT_lo + (size_t)rB*HD + k0 + cB*8;
            uint32_t off = (uint32_t)rB*144u + (uint32_t)cB*16u;
            *reinterpret_cast<uint4*>(Bs + off)         = *reinterpret_cast<const uint4*>(ph);
            *reinterpret_cast<uint4*>(Bs + 4608 + off)  = *reinterpret_cast<const uint4*>(pl);
        }
        __syncthreads();
        #pragma unroll
        for (int k = 0; k < 4; k++) {
            uint32_t kb = (uint32_t)k * 32u;
            uint32_t ah[4], al[4];
            ldsm_x4(ah, sbA_h + aRow + kb);
            ldsm_x4(al, sbA_l + aRow + kb);
            #pragma unroll
            for (int n = 0; n < 2; n++) {
                uint32_t bf[4];
                ldsm_x4(bf, bAddr + (uint32_t)(nh*2 + n)*(8u*144u) + kb);
                mma16816(acc[n], ah, bf);
                mma16816(acc[n], ah, bf + 2);
                mma16816(acc[n], al, bf);
            }
        }
    }
    // ---- fused epilogue: transpose tile, g1/g2 (+fp16 triplets), Wh2T fp16 ----
    __syncthreads();
    float* ts2 = reinterpret_cast<float*>(Ahp);          // [32 c][68]
    float* ao1s = reinterpret_cast<float*>(Alp);         // 32
    float* ao2s = reinterpret_cast<float*>(Alp + 128);   // 32
    float* fse2 = reinterpret_cast<float*>(Alp + 256);   // 3 x 64
    if (t < 32) { ao1s[t] = ao1[t]; ao2s[t] = ao2[t]; }
    int r0 = mt*16 + (lane >> 2);
    int r1 = r0 + 8;
    #pragma unroll
    for (int n = 0; n < 2; n++) {
        int c = nh*16 + n*8 + (lane & 3)*2;
        ts2[c*68 + r0]     = acc[n][0];
        ts2[(c+1)*68 + r0] = acc[n][1];
        ts2[c*68 + r1]     = acc[n][2];
        ts2[(c+1)*68 + r1] = acc[n][3];
    }
    __syncthreads();
    if (t < 64) {
        float g1 = 0.f, g2 = 0.f;
        #pragma unroll
        for (int c = 0; c < 32; c++) {
            float wv = ts2[c*68 + t];
            g1 += wv * ao1s[c];
            g2 += wv * ao2s[c];
        }
        int tid = b*NN + nd0 + t;
        g_G1R[tid] = make_float2(g1, expf(-0.8f*g1));
        fse2[t]       = g2;
        fse2[64 + t]  = expf(g2);
        fse2[128 + t] = expf(0.2f*g2);
    }
    {
        int c = t >> 3, nc = t & 7;
        uint32_t hw[4];
        #pragma unroll
        for (int p = 0; p < 4; p++)
            hw[p] = pk_h2(ts2[c*68 + nc*8 + 2*p], ts2[c*68 + nc*8 + 2*p + 1]);
        size_t off = ((size_t)(b*CC) + c)*NN + nd0 + nc*8;
        *reinterpret_cast<uint4*>(g_Wh2T + off) = *reinterpret_cast<uint4*>(hw);
    }
    __syncthreads();
    if (t < 32) {
        uint4 o;
        o.x = pk_h2(fse2[2*t],       fse2[2*t + 1]);
        o.y = pk_h2(fse2[64 + 2*t],  fse2[64 + 2*t + 1]);
        o.z = pk_h2(fse2[128 + 2*t], fse2[128 + 2*t + 1]);
        o.w = 0;
        g_G2H[(size_t)b*(NN/2) + nd0/2 + t] = o;
    }
}

// ---------------- K5: layer-2 attention, pipelined single-barrier tiles ----------------
// smem: A0 @0, A1 @9216 (64x72 fp16); B0 @18432, B1 @23040 (32x72);
// g2s @27648 (uint4[2][32]). Total 28672.
__global__ __launch_bounds__(256) void k5_attn2_mma(float* __restrict__ out) {
    __shared__ __align__(16) char sm5[28672];
    uint4* g2s = reinterpret_cast<uint4*>(sm5 + 27648);
    uint32_t sb = smem_u32(sm5);

    int t = threadIdx.x;
    int warp = t >> 5, lane = t & 31;
    int i0 = blockIdx.x * 64;
    int b = blockIdx.y;

    int i = t & 63, jq = t >> 6;
    float2 g1r = g_G1R[b*NN + i0 + i];
    uint32_t negg = f2h2(-g1r.x);
    uint32_t rmulh = f2h2(g1r.y);
    const __half* bsrc = g_Wh2T + (size_t)(b*CC)*NN;
    const uint4* g2g = g_G2H + (size_t)b*(NN/2);
    const unsigned* adjb = g_adjbT + ((size_t)(b<<6))*NN + i0 + i;

    int mt = warp >> 1, nh = warp & 1;
    float acc[2][4];
    acc[0][0]=0.f; acc[0][1]=0.f; acc[0][2]=0.f; acc[0][3]=0.f;
    acc[1][0]=0.f; acc[1][1]=0.f; acc[1][2]=0.f; acc[1][3]=0.f;
    float accz[4] = {0.f, 0.f, 0.f, 0.f};
    uint32_t bzf[2];
    bzf[0] = (lane < 4) ? 0x3C003C00u : 0u;
    bzf[1] = bzf[0];

    uint32_t aRow = (uint32_t)(mt*16 + (lane & 15)) * 144u + ((lane & 16) ? 16u : 0u);
    uint32_t bFrag = (uint32_t)(lane & 7) * 144u + ((lane & 16) ? 1152u : 0u)
                   + (uint32_t)(lane & 8) * 2u + (uint32_t)nh * 2304u;
    uint32_t aWr = (uint32_t)i*144u + (uint32_t)jq*32u;

    int rB = t >> 3, cB = t & 7;
    const __half* pB = bsrc + (size_t)rB*NN + cB*8;
    uint32_t bStOff = (uint32_t)rB*144u + (uint32_t)cB*16u;

    // ---- prologue ----
    CP_ASYNC16(sb + 18432u + bStOff, pB);
    CP_COMMIT();
    if (t < 32) g2s[t] = __ldg(&g2g[t]);
    __syncthreads();
    wphase4(sm5, aWr, &g2s[jq*8], adjb[(jq>>1)*NN] >> ((jq & 1)*16) & 0xFFFFu,
            negg, rmulh, 2);
    if (t < 32) g2s[32 + t] = __ldg(&g2g[32 + t]);

    for (int jt = 0; jt < 32; jt++) {
        int pb = jt & 1;
        CP_WAIT(0);
        __syncthreads();
        if (jt < 31) {
            CP_ASYNC16(sb + 18432u + (uint32_t)(pb^1)*4608u + bStOff, pB + (jt+1)*64);
            CP_COMMIT();
        }
        // ---- MMA(jt) first ----
        uint32_t aBase = sb + (uint32_t)pb*9216u + aRow;
        uint32_t bBase = sb + 18432u + (uint32_t)pb*4608u + bFrag;
        #pragma unroll
        for (int k = 0; k < 4; k++) {
            uint32_t kb = (uint32_t)k * 32u;
            uint32_t ah[4];
            ldsm_x4(ah, aBase + kb);
            mma16816h(accz, ah, bzf);
            uint32_t bf[4];
            ldsm_x4(bf, bBase + kb);
            mma16816h(acc[0], ah, bf);
            mma16816h(acc[1], ah, bf + 2);
        }
        // ---- weights(jt+1) -> A[pb^1] ----
        if (jt < 31) {
            unsigned bwf = adjb[((jt+1)*2 + (jq>>1))*NN];
            unsigned bw = (bwf >> ((jq & 1)*16)) & 0xFFFFu;
            wphase4(sm5, (uint32_t)(pb^1)*9216u + aWr,
                    &g2s[(uint32_t)(pb^1)*32 + jq*8], bw, negg, rmulh, 2);
        }
        if (jt < 30 && t < 32)
            g2s[pb*32 + t] = __ldg(&g2g[(jt+2)*32 + t]);
    }
    float z0 = __shfl_sync(0xffffffffu, accz[0], lane & 28);
    float z1 = __shfl_sync(0xffffffffu, accz[2], lane & 28);
    if (z0 < 1e-30f) z0 = 1.f;
    if (z1 < 1e-30f) z1 = 1.f;
    float invz0 = 1.f / z0, invz1 = 1.f / z1;
    int r0 = mt*16 + (lane >> 2);
    int r1 = r0 + 8;
    #pragma unroll
    for (int n = 0; n < 2; n++) {
        int c0 = nh*16 + n*8 + (lane & 3)*2;
        float2 o0 = make_float2(acc[n][0]*invz0, acc[n][1]*invz0);
        float2 o1 = make_float2(acc[n][2]*invz1, acc[n][3]*invz1);
        *reinterpret_cast<float2*>(&out[(size_t)(b*NN + i0 + r0)*CC + c0]) = o0;
        *reinterpret_cast<float2*>(&out[(size_t)(b*NN + i0 + r1)*CC + c0]) = o1;
    }
}

extern "C" void kernel_launch(void* const* d_in, const int* in_sizes, int n_in,
                              void* d_out, int out_size) {
    const float* x   = (const float*)d_in[0];
    const int*   adj = (const int*)  d_in[1];
    const float* W   = (const float*)d_in[2];
    const float* a1  = (const float*)d_in[3];
    const float* a2  = (const float*)d_in[4];
    const float* Wo  = (const float*)d_in[5];
    const float* ao1 = (const float*)d_in[6];
    const float* ao2 = (const float*)d_in[7];
    float* out = (float*)d_out;

    cudaFuncSetAttribute(k3_attn1_mma,
                         cudaFuncAttributeMaxDynamicSharedMemorySize, K3_SMEM);
    cudaFuncSetAttribute(k1_hmma,
                         cudaFuncAttributeMaxDynamicSharedMemorySize, K1_SMEM);

    kws_split<<<64, 256>>>(W);                        // W -> WcatT bf16 hi/lo
    k4w_split<<<16, 256>>>(Wo);                       // Wo -> WoT bf16 hi/lo
    k0_mask<<<1024, 256>>>(adj);                      // adj -> transposed bitmask
    k1_hmma<<<dim3(8, 64), 256, K1_SMEM>>>(x, a1, a2);// Wh + WhT fp16 + f-triplets
    k3_attn1_mma<<<dim3(16, 8, 4), 256, K3_SMEM>>>(); // layer-1 attn (pipelined)
    k4_hmma<<<128, 256>>>(ao1, ao2);                  // Wh2T fp16 + g-triplets
    k5_attn2_mma<<<dim3(32, 4), 256>>>(out);          // layer-2 attn (pipelined)
}